// round 13
// baseline (speedup 1.0000x reference)
#include <cuda_runtime.h>

#define DIM 1024
#define NPAIRS 512
#define ROWS_PER_BLK 8
#define THREADS 256        // 8 warps, one row per warp

// Composite complex butterfly coefficients, one per adjacent pair.
__device__ float2 g_coef[NPAIRS];

// W_j = prod_{l=1..9} (a_l - i b_l); level-l params at offset 4096 - 2^(12-l),
// block index for pair j is j >> (l-1). (l=0 params unused: bs<2.)
__global__ void coef_kernel(const float* __restrict__ params) {
    int j = blockIdx.x * blockDim.x + threadIdx.x;
    if (j >= NPAIRS) return;
    float Wr = 1.0f, Wi = 0.0f;
#pragma unroll
    for (int l = 1; l <= 9; ++l) {
        int off = 4096 - (1 << (12 - l));
        int blk = j >> (l - 1);
        float a = params[off + 2 * blk];
        float b = params[off + 2 * blk + 1];
        float nr = Wr * a + Wi * b;     // (Wr + i Wi) *= (a - i b)
        float ni = Wi * a - Wr * b;
        Wr = nr; Wi = ni;
    }
    g_coef[j] = make_float2(Wr, Wi);
}

// Warp-per-row main kernel (empirically fastest configuration: 36.4us).
// Coefficients staged into smem with ONE LDG.128 per thread (no scattered
// param loads in the hot kernel), row loads front-batched MLP=8 evict-first,
// single fused warp reduction, evict-first stores.
__global__ __launch_bounds__(THREADS) void hyper_butterfly_kernel(
    const float4* __restrict__ x, float4* __restrict__ out)
{
    __shared__ float4 wsh[NPAIRS / 2];   // 256 float4 = 4 KB

    const int tid  = threadIdx.x;
    const int lane = tid & 31;
    const int wid  = tid >> 5;

    // ---- stage coefficient table: one float4 per thread ----
    wsh[tid] = ((const float4*)g_coef)[tid];

    const size_t base = ((size_t)blockIdx.x * ROWS_PER_BLK + wid) * (DIM / 4);

    // ---- front-batched row loads (MLP=8, streaming) ----
    float4 v[8];
#pragma unroll
    for (int i = 0; i < 8; ++i) v[i] = __ldcs(x + base + lane + 32 * i);

    __syncthreads();

    // ---- partial sums: ||x||^2 and ||W z||^2 = sum |W_j|^2 |z_j|^2 ----
    float ss = 0.0f, ss2 = 0.0f;
#pragma unroll
    for (int i = 0; i < 8; ++i) {
        float4 vv = v[i];
        float4 ww = wsh[lane + 32 * i];      // conflict-free LDS.128
        float p0 = vv.x * vv.x + vv.y * vv.y;
        float p1 = vv.z * vv.z + vv.w * vv.w;
        float q0 = ww.x * ww.x + ww.y * ww.y;
        float q1 = ww.z * ww.z + ww.w * ww.w;
        ss  += p0 + p1;
        ss2 += q0 * p0 + q1 * p1;
    }

    // ---- single warp reduction, two interleaved trees ----
#pragma unroll
    for (int o = 16; o; o >>= 1) {
        ss  += __shfl_xor_sync(0xFFFFFFFFu, ss,  o);
        ss2 += __shfl_xor_sync(0xFFFFFFFFu, ss2, o);
    }

    float n  = sqrtf(ss);
    float s1 = (n > 0.0f) ? (atanhf(n) / n) : 1.0f;      // log_map(0,x) scale
    float vn = fmaxf(s1 * sqrtf(ss2), 1e-8f);            // ||u||
    float s  = s1 * (tanhf(vn) / vn);                    // total scale

    // ---- rotate, scale, streaming store ----
#pragma unroll
    for (int i = 0; i < 8; ++i) {
        float4 vv = v[i];
        float4 ww = wsh[lane + 32 * i];
        float4 o4;
        o4.x = s * (ww.x * vv.x - ww.y * vv.y);
        o4.y = s * (ww.y * vv.x + ww.x * vv.y);
        o4.z = s * (ww.z * vv.z - ww.w * vv.w);
        o4.w = s * (ww.w * vv.z + ww.z * vv.w);
        __stcs(out + base + lane + 32 * i, o4);
    }
}

extern "C" void kernel_launch(void* const* d_in, const int* in_sizes, int n_in,
                              void* d_out, int out_size) {
    const float* xp = (const float*)d_in[0];
    const float* pp = (const float*)d_in[1];
    long long n0 = in_sizes[0], n1 = in_sizes[1];
    if (n0 < n1) { const float* tmp = xp; xp = pp; pp = tmp; long long ts = n0; n0 = n1; n1 = ts; }
    int rows = (int)(n0 / DIM);

    coef_kernel<<<1, NPAIRS>>>(pp);
    hyper_butterfly_kernel<<<rows / ROWS_PER_BLK, THREADS>>>(
        (const float4*)xp, (float4*)d_out);
}

// round 14
// speedup vs baseline: 1.1331x; 1.1331x over previous
#include <cuda_runtime.h>

#define DIM 1024
#define NPAIRS 512
#define ROWS_PER_BLK 8
#define THREADS 256        // 8 warps, one row per warp

// Single fused kernel — best measured configuration (45.12us total, round 8).
//
// Math (base point 0, c=1):
//   log_map(0,x) = atanh(||x||)/||x|| * x                     (scale s1)
//   butterfly    = per adjacent pair p=(2j,2j+1): complex multiply by
//                  W_p = prod_{l=1..9} (a_l[p>>(l-1)] - i*b_l[p>>(l-1)]),
//                  level-l params at offset 4096 - 2^(12-l)   (l=0 unused)
//   exp_map(0,u) = tanh(||u||)/max(||u||,1e-8) * u
//
// Coef phase: thread t computes {W_{2t}, W_{2t+1}} via 9 independent
// up-front loads (MLP=9) + a short FMA chain, one STS, one barrier — fully
// hidden under the front-batched row loads (verified round 10: halving its
// execution count changed nothing).
__global__ __launch_bounds__(THREADS) void hyper_butterfly_fused(
    const float* __restrict__ params,
    const float4* __restrict__ x,
    float4* __restrict__ out)
{
    __shared__ float4 wsh[THREADS];   // wsh[t] = {W_2t.re, W_2t.im, W_2t+1.re, W_2t+1.im}

    const int tid  = threadIdx.x;
    const int lane = tid & 31;
    const int wid  = tid >> 5;

    // ---- coef phase: 9 independent loads up front ----
    float2 f[8];
#pragma unroll
    for (int l = 2; l <= 9; ++l) {
        const float2* lvl = (const float2*)(params + 4096 - (1 << (12 - l)));
        f[l - 2] = __ldg(lvl + (tid >> (l - 2)));          // (a_l, b_l)
    }
    float4 g1 = __ldg((const float4*)(params + 2048) + tid); // level-1 pair params

    float Pr = 1.0f, Pi = 0.0f;                // prefix over levels 2..9
#pragma unroll
    for (int i = 0; i < 8; ++i) {
        float a = f[i].x, b = f[i].y;
        float nr = a * Pr + b * Pi;            // (a - i b) * (Pr + i Pi)
        float ni = a * Pi - b * Pr;
        Pr = nr; Pi = ni;
    }
    float4 wv;
    wv.x = g1.x * Pr + g1.y * Pi;
    wv.y = g1.x * Pi - g1.y * Pr;
    wv.z = g1.z * Pr + g1.w * Pi;
    wv.w = g1.z * Pi - g1.w * Pr;
    wsh[tid] = wv;

    // ---- front-batched row loads (MLP=8, streaming), then barrier ----
    const size_t base = ((size_t)blockIdx.x * ROWS_PER_BLK + wid) * (DIM / 4);
    float4 v[8];
#pragma unroll
    for (int i = 0; i < 8; ++i) v[i] = __ldcs(x + base + lane + 32 * i);

    __syncthreads();   // covers wsh stores; v-load latency overlaps this + LDS below

    // ---- partial sums: ||x||^2 and ||W z||^2 = sum |W_j|^2 |z_j|^2 ----
    float ss = 0.0f, ss2 = 0.0f;
#pragma unroll
    for (int i = 0; i < 8; ++i) {
        float4 vv = v[i];
        float4 ww = wsh[lane + 32 * i];        // conflict-free LDS.128
        float p0 = vv.x * vv.x + vv.y * vv.y;
        float p1 = vv.z * vv.z + vv.w * vv.w;
        float q0 = ww.x * ww.x + ww.y * ww.y;
        float q1 = ww.z * ww.z + ww.w * ww.w;
        ss  += p0 + p1;
        ss2 += q0 * p0 + q1 * p1;
    }

    // ---- single warp reduction, two interleaved trees ----
#pragma unroll
    for (int o = 16; o; o >>= 1) {
        ss  += __shfl_xor_sync(0xFFFFFFFFu, ss,  o);
        ss2 += __shfl_xor_sync(0xFFFFFFFFu, ss2, o);
    }

    float n  = sqrtf(ss);
    float s1 = (n > 0.0f) ? (atanhf(n) / n) : 1.0f;      // log_map(0,x) scale
    float vn = fmaxf(s1 * sqrtf(ss2), 1e-8f);            // ||u||
    float s  = s1 * (tanhf(vn) / vn);                    // total scale

    // ---- rotate, scale, streaming store ----
#pragma unroll
    for (int i = 0; i < 8; ++i) {
        float4 vv = v[i];
        float4 ww = wsh[lane + 32 * i];
        float4 o4;
        o4.x = s * (ww.x * vv.x - ww.y * vv.y);
        o4.y = s * (ww.y * vv.x + ww.x * vv.y);
        o4.z = s * (ww.z * vv.z - ww.w * vv.w);
        o4.w = s * (ww.w * vv.z + ww.z * vv.w);
        __stcs(out + base + lane + 32 * i, o4);
    }
}

extern "C" void kernel_launch(void* const* d_in, const int* in_sizes, int n_in,
                              void* d_out, int out_size) {
    const float* xp = (const float*)d_in[0];
    const float* pp = (const float*)d_in[1];
    long long n0 = in_sizes[0], n1 = in_sizes[1];
    if (n0 < n1) { const float* tmp = xp; xp = pp; pp = tmp; long long ts = n0; n0 = n1; n1 = ts; }
    int rows = (int)(n0 / DIM);

    hyper_butterfly_fused<<<rows / ROWS_PER_BLK, THREADS>>>(
        pp, (const float4*)xp, (float4*)d_out);
}